// round 1
// baseline (speedup 1.0000x reference)
#include <cuda_runtime.h>
#include <cuda_bf16.h>
#include <cstdint>

// Problem constants
#define BB 8
#define SS 1024
#define DD 512
#define HH 8
#define HD 64
#define FF 2048
#define NROWS (BB*SS)          // 8192

// ---------------- scratch (device globals; no allocation allowed) ----------
__device__ float g_h  [NROWS*DD];
__device__ float g_q  [NROWS*DD];
__device__ float g_k  [NROWS*DD];
__device__ float g_v  [NROWS*DD];
__device__ float g_ctx[NROWS*DD];
__device__ float g_x2 [NROWS*DD];
__device__ float g_h2 [NROWS*DD];
__device__ float g_ff [NROWS*FF];

// ---------------- RMSNorm: one block per row (512 elems) -------------------
__global__ __launch_bounds__(256) void rmsnorm_kernel(
    const float* __restrict__ x, const float* __restrict__ w, float* __restrict__ out)
{
    int row = blockIdx.x;
    const float* xr = x + (size_t)row * DD;
    int t = threadIdx.x;
    float v0 = xr[t];
    float v1 = xr[t + 256];
    float ss = v0 * v0 + v1 * v1;
    #pragma unroll
    for (int off = 16; off; off >>= 1)
        ss += __shfl_xor_sync(0xffffffffu, ss, off);
    __shared__ float red[8];
    if ((t & 31) == 0) red[t >> 5] = ss;
    __syncthreads();
    float total = 0.f;
    #pragma unroll
    for (int i = 0; i < 8; i++) total += red[i];
    float inv = rsqrtf(total * (1.0f / DD) + 1e-6f);
    float* orow = out + (size_t)row * DD;
    orow[t]       = w[t]       * v0 * inv;
    orow[t + 256] = w[t + 256] * v1 * inv;
}

// ---------------- Generic SGEMM: C = epi(A[M,K] @ B[N,K]^T (+R)) -----------
// EPI: 0 = none, 1 = relu, 2 = residual add
#define GBM 128
#define GBN 64
#define GBK 16

template <int EPI>
__global__ __launch_bounds__(256) void gemm_kernel(
    const float* __restrict__ A, const float* __restrict__ B,
    const float* __restrict__ R, float* __restrict__ C,
    int M, int N, int K)
{
    __shared__ float As[GBK][GBM];
    __shared__ float Bs[GBK][GBN];

    int tid = threadIdx.x;
    int tx = tid & 15;          // 0..15 -> N microtile
    int ty = tid >> 4;          // 0..15 -> M microtile
    int bm = blockIdx.y * GBM;
    int bn = blockIdx.x * GBN;

    float acc[8][4];
    #pragma unroll
    for (int i = 0; i < 8; i++)
        #pragma unroll
        for (int j = 0; j < 4; j++) acc[i][j] = 0.f;

    int ar  = tid >> 2;         // 0..63
    int ac4 = tid & 3;          // 0..3 (float4 column)
    const float* Ap0 = A + (size_t)(bm + ar)      * K + ac4 * 4;
    const float* Ap1 = A + (size_t)(bm + ar + 64) * K + ac4 * 4;
    const float* Bp  = B + (size_t)(bn + ar)      * K + ac4 * 4;

    for (int kt = 0; kt < K; kt += GBK) {
        float4 a0 = *(const float4*)(Ap0 + kt);
        float4 a1 = *(const float4*)(Ap1 + kt);
        float4 b0 = *(const float4*)(Bp  + kt);
        As[ac4*4+0][ar]    = a0.x; As[ac4*4+1][ar]    = a0.y;
        As[ac4*4+2][ar]    = a0.z; As[ac4*4+3][ar]    = a0.w;
        As[ac4*4+0][ar+64] = a1.x; As[ac4*4+1][ar+64] = a1.y;
        As[ac4*4+2][ar+64] = a1.z; As[ac4*4+3][ar+64] = a1.w;
        Bs[ac4*4+0][ar]    = b0.x; Bs[ac4*4+1][ar]    = b0.y;
        Bs[ac4*4+2][ar]    = b0.z; Bs[ac4*4+3][ar]    = b0.w;
        __syncthreads();

        #pragma unroll
        for (int kk = 0; kk < GBK; kk++) {
            float a[8], b[4];
            #pragma unroll
            for (int i = 0; i < 8; i++) a[i] = As[kk][ty*8 + i];
            #pragma unroll
            for (int j = 0; j < 4; j++) b[j] = Bs[kk][tx*4 + j];
            #pragma unroll
            for (int i = 0; i < 8; i++)
                #pragma unroll
                for (int j = 0; j < 4; j++)
                    acc[i][j] = fmaf(a[i], b[j], acc[i][j]);
        }
        __syncthreads();
    }

    #pragma unroll
    for (int i = 0; i < 8; i++) {
        size_t row = (size_t)(bm + ty*8 + i);
        size_t off = row * N + bn + tx*4;
        float4 v;
        v.x = acc[i][0]; v.y = acc[i][1]; v.z = acc[i][2]; v.w = acc[i][3];
        if (EPI == 1) {
            v.x = fmaxf(v.x, 0.f); v.y = fmaxf(v.y, 0.f);
            v.z = fmaxf(v.z, 0.f); v.w = fmaxf(v.w, 0.f);
        }
        if (EPI == 2) {
            float4 r = *(const float4*)(R + off);
            v.x += r.x; v.y += r.y; v.z += r.z; v.w += r.w;
        }
        *(float4*)(C + off) = v;
    }
}

// ---------------- Flash attention with additive bias -----------------------
// grid: (S/64, H, B), 256 threads. Q/K/V in [B,S,D] layout (head = cols h*64..).
// ctx written back to [B,S,D].
__global__ __launch_bounds__(256) void attn_kernel(
    const float* __restrict__ Q, const float* __restrict__ K,
    const float* __restrict__ V, const float* __restrict__ bias,
    float* __restrict__ ctx)
{
    __shared__ float QsT[64][64];   // [dim][query]
    __shared__ float KV [64][64];   // K phase: [dim][key]; V phase: [key][hd]
    __shared__ float Ps [64][64];   // [query][key]

    int qt = blockIdx.x, h = blockIdx.y, b = blockIdx.z;
    int tid = threadIdx.x;
    int tx = tid & 15, ty = tid >> 4;

    // Load Q tile (64 queries x 64 dims), store transposed
    #pragma unroll
    for (int it = 0; it < 4; it++) {
        int idx = tid + it * 256;
        int row = idx >> 4;          // query within tile
        int c4  = idx & 15;
        float4 qv = *(const float4*)(Q + (size_t)(b*SS + qt*64 + row) * DD + h*HD + c4*4);
        QsT[c4*4+0][row] = qv.x; QsT[c4*4+1][row] = qv.y;
        QsT[c4*4+2][row] = qv.z; QsT[c4*4+3][row] = qv.w;
    }

    float m[4], l[4], O[4][4];
    #pragma unroll
    for (int i = 0; i < 4; i++) {
        m[i] = -1e30f; l[i] = 0.f;
        #pragma unroll
        for (int j = 0; j < 4; j++) O[i][j] = 0.f;
    }

    for (int kt = 0; kt < SS/64; kt++) {
        // Load K tile transposed into KV ([dim][key])
        #pragma unroll
        for (int it = 0; it < 4; it++) {
            int idx = tid + it * 256;
            int row = idx >> 4;      // key within tile
            int c4  = idx & 15;
            float4 kv = *(const float4*)(K + (size_t)(b*SS + kt*64 + row) * DD + h*HD + c4*4);
            KV[c4*4+0][row] = kv.x; KV[c4*4+1][row] = kv.y;
            KV[c4*4+2][row] = kv.z; KV[c4*4+3][row] = kv.w;
        }
        __syncthreads();

        // S = Q K^T  (4x4 microtile per thread)
        float s[4][4];
        #pragma unroll
        for (int i = 0; i < 4; i++)
            #pragma unroll
            for (int j = 0; j < 4; j++) s[i][j] = 0.f;
        #pragma unroll
        for (int kk = 0; kk < 64; kk++) {
            float a[4], bb[4];
            #pragma unroll
            for (int i = 0; i < 4; i++) a[i]  = QsT[kk][ty*4 + i];
            #pragma unroll
            for (int j = 0; j < 4; j++) bb[j] = KV [kk][tx*4 + j];
            #pragma unroll
            for (int i = 0; i < 4; i++)
                #pragma unroll
                for (int j = 0; j < 4; j++)
                    s[i][j] = fmaf(a[i], bb[j], s[i][j]);
        }

        // add bias + online softmax
        #pragma unroll
        for (int i = 0; i < 4; i++) {
            size_t boff = ((size_t)(b*HH + h) * SS + (qt*64 + ty*4 + i)) * SS
                          + kt*64 + tx*4;
            float4 bv = *(const float4*)(bias + boff);
            s[i][0] += bv.x; s[i][1] += bv.y; s[i][2] += bv.z; s[i][3] += bv.w;

            float mt = fmaxf(fmaxf(s[i][0], s[i][1]), fmaxf(s[i][2], s[i][3]));
            #pragma unroll
            for (int off = 8; off; off >>= 1)
                mt = fmaxf(mt, __shfl_xor_sync(0xffffffffu, mt, off, 16));
            float mn = fmaxf(m[i], mt);
            float corr = __expf(m[i] - mn);
            float rs = 0.f;
            #pragma unroll
            for (int j = 0; j < 4; j++) {
                float p = __expf(s[i][j] - mn);
                Ps[ty*4 + i][tx*4 + j] = p;
                rs += p;
            }
            #pragma unroll
            for (int off = 8; off; off >>= 1)
                rs += __shfl_xor_sync(0xffffffffu, rs, off, 16);
            l[i] = l[i] * corr + rs;
            m[i] = mn;
            #pragma unroll
            for (int j = 0; j < 4; j++) O[i][j] *= corr;
        }
        __syncthreads();   // Ps visible; KV reads (S compute) finished

        // Load V tile into KV ([key][hd], natural layout)
        #pragma unroll
        for (int it = 0; it < 4; it++) {
            int idx = tid + it * 256;
            int row = idx >> 4;      // key within tile
            int c4  = idx & 15;
            float4 vv = *(const float4*)(V + (size_t)(b*SS + kt*64 + row) * DD + h*HD + c4*4);
            *(float4*)&KV[row][c4*4] = vv;
        }
        __syncthreads();

        // O += P @ V
        #pragma unroll
        for (int kk = 0; kk < 64; kk++) {
            float a[4], bb[4];
            #pragma unroll
            for (int i = 0; i < 4; i++) a[i]  = Ps[ty*4 + i][kk];
            #pragma unroll
            for (int j = 0; j < 4; j++) bb[j] = KV[kk][tx*4 + j];
            #pragma unroll
            for (int i = 0; i < 4; i++)
                #pragma unroll
                for (int j = 0; j < 4; j++)
                    O[i][j] = fmaf(a[i], bb[j], O[i][j]);
        }
        __syncthreads();   // done reading Ps/KV before next tile overwrites
    }

    // write ctx (normalize by l)
    #pragma unroll
    for (int i = 0; i < 4; i++) {
        float invl = 1.0f / l[i];
        size_t off = (size_t)(b*SS + qt*64 + ty*4 + i) * DD + h*HD + tx*4;
        float4 v;
        v.x = O[i][0] * invl; v.y = O[i][1] * invl;
        v.z = O[i][2] * invl; v.w = O[i][3] * invl;
        *(float4*)(ctx + off) = v;
    }
}

// ---------------- launch ---------------------------------------------------
extern "C" void kernel_launch(void* const* d_in, const int* in_sizes, int n_in,
                              void* d_out, int out_size)
{
    const float* Wk   = (const float*)d_in[0];   // primals_1 (D,D)
    const float* Wo   = (const float*)d_in[1];   // primals_2 (D,D)
    const float* Wq   = (const float*)d_in[2];   // primals_3 (D,D)
    const float* Wv   = (const float*)d_in[3];   // primals_4 (D,D)
    const float* ln1  = (const float*)d_in[4];   // primals_5 (D,)
    const float* W1   = (const float*)d_in[5];   // primals_6 (F,D)
    const float* W2   = (const float*)d_in[6];   // primals_7 (D,F)
    const float* ln2  = (const float*)d_in[7];   // primals_8 (D,)
    const float* x    = (const float*)d_in[8];   // primals_9 (B,S,D)
    const float* bias = (const float*)d_in[9];   // primals_10 (B,H,S,S)
    float* out = (float*)d_out;

    float *ph, *pq, *pk, *pv, *pctx, *px2, *ph2, *pff;
    cudaGetSymbolAddress((void**)&ph,   g_h);
    cudaGetSymbolAddress((void**)&pq,   g_q);
    cudaGetSymbolAddress((void**)&pk,   g_k);
    cudaGetSymbolAddress((void**)&pv,   g_v);
    cudaGetSymbolAddress((void**)&pctx, g_ctx);
    cudaGetSymbolAddress((void**)&px2,  g_x2);
    cudaGetSymbolAddress((void**)&ph2,  g_h2);
    cudaGetSymbolAddress((void**)&pff,  g_ff);

    dim3 gD(DD/GBN, NROWS/GBM);    // N=512
    dim3 gF(FF/GBN, NROWS/GBM);    // N=2048

    // 1. h = rmsnorm(x, ln1)
    rmsnorm_kernel<<<NROWS, 256>>>(x, ln1, ph);
    // 2-4. Q/K/V projections
    gemm_kernel<0><<<gD, 256>>>(ph, Wq, nullptr, pq, NROWS, DD, DD);
    gemm_kernel<0><<<gD, 256>>>(ph, Wk, nullptr, pk, NROWS, DD, DD);
    gemm_kernel<0><<<gD, 256>>>(ph, Wv, nullptr, pv, NROWS, DD, DD);
    // 5. attention
    dim3 ga(SS/64, HH, BB);
    attn_kernel<<<ga, 256>>>(pq, pk, pv, bias, pctx);
    // 6. x2 = x + ctx @ Wo^T
    gemm_kernel<2><<<gD, 256>>>(pctx, Wo, x, px2, NROWS, DD, DD);
    // 7. h2 = rmsnorm(x2, ln2)
    rmsnorm_kernel<<<NROWS, 256>>>(px2, ln2, ph2);
    // 8. ff = relu(h2 @ W1^T)
    gemm_kernel<1><<<gF, 256>>>(ph2, W1, nullptr, pff, NROWS, FF, DD);
    // 9. out = x2 + ff @ W2^T
    gemm_kernel<2><<<gD, 256>>>(pff, W2, px2, out, NROWS, DD, FF);
}

// round 3
// speedup vs baseline: 1.9717x; 1.9717x over previous
#include <cuda_runtime.h>
#include <cuda_bf16.h>
#include <cstdint>

// Problem constants
#define BB 8
#define SS 1024
#define DD 512
#define HH 8
#define HD 64
#define FF 2048
#define NROWS (BB*SS)          // 8192

// ---------------- helpers ----------------------------------------------------
__device__ __forceinline__ uint32_t smem_to_u32(const void* p) {
    uint32_t a;
    asm("{ .reg .u64 t; cvta.to.shared.u64 t, %1; cvt.u32.u64 %0, t; }"
        : "=r"(a) : "l"(p));
    return a;
}
__device__ __forceinline__ void cpasync16(uint32_t s, const void* g) {
    asm volatile("cp.async.cg.shared.global [%0], [%1], 16;" :: "r"(s), "l"(g));
}
__device__ __forceinline__ void cpasync_commit() {
    asm volatile("cp.async.commit_group;" ::: "memory");
}
__device__ __forceinline__ void cpasync_wait1() {
    asm volatile("cp.async.wait_group 1;" ::: "memory");
}
__device__ __forceinline__ void cpasync_wait0() {
    asm volatile("cp.async.wait_group 0;" ::: "memory");
}
__device__ __forceinline__ void ldsm4(uint32_t* r, uint32_t addr) {
    asm volatile("ldmatrix.sync.aligned.m8n8.x4.shared.b16 {%0,%1,%2,%3}, [%4];"
        : "=r"(r[0]), "=r"(r[1]), "=r"(r[2]), "=r"(r[3]) : "r"(addr));
}
__device__ __forceinline__ void mma16816(float* c, const uint32_t* a, const uint32_t* b) {
    asm volatile(
        "mma.sync.aligned.m16n8k16.row.col.f32.bf16.bf16.f32 "
        "{%0,%1,%2,%3}, {%4,%5,%6,%7}, {%8,%9}, {%0,%1,%2,%3};"
        : "+f"(c[0]), "+f"(c[1]), "+f"(c[2]), "+f"(c[3])
        : "r"(a[0]), "r"(a[1]), "r"(a[2]), "r"(a[3]), "r"(b[0]), "r"(b[1]));
}
__device__ __forceinline__ void split_bf16(float v, __nv_bfloat16& h, __nv_bfloat16& l) {
    h = __float2bfloat16_rn(v);
    l = __float2bfloat16_rn(v - __bfloat162float(h));
}

// ---------------- scratch (device globals) ----------------------------------
__device__ __nv_bfloat16 g_hhi [NROWS*DD], g_hlo [NROWS*DD];
__device__ float         g_q   [NROWS*DD], g_k [NROWS*DD], g_v [NROWS*DD];
__device__ __nv_bfloat16 g_chi [NROWS*DD], g_clo [NROWS*DD];
__device__ float         g_x2  [NROWS*DD];
__device__ __nv_bfloat16 g_h2hi[NROWS*DD], g_h2lo[NROWS*DD];
__device__ __nv_bfloat16 g_fhi [NROWS*FF], g_flo [NROWS*FF];
__device__ __nv_bfloat16 g_wqhi[DD*DD], g_wqlo[DD*DD];
__device__ __nv_bfloat16 g_wkhi[DD*DD], g_wklo[DD*DD];
__device__ __nv_bfloat16 g_wvhi[DD*DD], g_wvlo[DD*DD];
__device__ __nv_bfloat16 g_wohi[DD*DD], g_wolo[DD*DD];
__device__ __nv_bfloat16 g_w1hi[FF*DD], g_w1lo[FF*DD];
__device__ __nv_bfloat16 g_w2hi[DD*FF], g_w2lo[DD*FF];

// ---------------- fp32 -> (hi, lo) bf16 conversion --------------------------
__global__ __launch_bounds__(256) void cvt_kernel(
    const float* __restrict__ x, __nv_bfloat16* __restrict__ hi,
    __nv_bfloat16* __restrict__ lo, int n4)
{
    int i = blockIdx.x * 256 + threadIdx.x;
    if (i >= n4) return;
    float4 v = ((const float4*)x)[i];
    __nv_bfloat16 h[4], l[4];
    split_bf16(v.x, h[0], l[0]); split_bf16(v.y, h[1], l[1]);
    split_bf16(v.z, h[2], l[2]); split_bf16(v.w, h[3], l[3]);
    *(uint2*)(hi + (size_t)i * 4) = *(uint2*)h;
    *(uint2*)(lo + (size_t)i * 4) = *(uint2*)l;
}

// ---------------- RMSNorm: writes hi/lo bf16 ---------------------------------
__global__ __launch_bounds__(256) void rmsnorm_kernel(
    const float* __restrict__ x, const float* __restrict__ w,
    __nv_bfloat16* __restrict__ ohi, __nv_bfloat16* __restrict__ olo)
{
    int row = blockIdx.x;
    const float* xr = x + (size_t)row * DD;
    int t = threadIdx.x;
    float v0 = xr[t];
    float v1 = xr[t + 256];
    float ss = v0 * v0 + v1 * v1;
    #pragma unroll
    for (int off = 16; off; off >>= 1)
        ss += __shfl_xor_sync(0xffffffffu, ss, off);
    __shared__ float red[8];
    if ((t & 31) == 0) red[t >> 5] = ss;
    __syncthreads();
    float total = 0.f;
    #pragma unroll
    for (int i = 0; i < 8; i++) total += red[i];
    float inv = rsqrtf(total * (1.0f / DD) + 1e-6f);
    float o0 = w[t] * v0 * inv;
    float o1 = w[t + 256] * v1 * inv;
    __nv_bfloat16 h, l;
    size_t base = (size_t)row * DD;
    split_bf16(o0, h, l); ohi[base + t] = h;       olo[base + t] = l;
    split_bf16(o1, h, l); ohi[base + t + 256] = h; olo[base + t + 256] = l;
}

// ---------------- split-bf16 tensor-core GEMM (mma.sync) ---------------------
// C[M,N] = epi( A[M,K] @ B[N,K]^T (+R) ), A/B given as bf16 hi/lo pairs.
// EPI: 0 = write fp32  1 = relu -> write bf16 hi/lo  2 = +R -> write fp32
// 128x128 CTA tile, K-chunk 64, 2-stage cp.async double buffer.
// SMEM per stage: Ahi(16K) Alo(16K) Bhi(16K) Blo(16K) = 64KB; 2 stages = 128KB.
#define STG 65536
#define OFF_ALO 16384
#define OFF_BHI 32768
#define OFF_BLO 49152
// swizzled byte offset within a [128 x 64 bf16] tile
#define TSWZ(r, c16) ((uint32_t)((r) * 128 + (((c16) ^ ((r) & 7)) << 4)))

template <int EPI>
__global__ __launch_bounds__(256) void gemm_mma_kernel(
    const __nv_bfloat16* __restrict__ Ahi, const __nv_bfloat16* __restrict__ Alo,
    const __nv_bfloat16* __restrict__ Bhi, const __nv_bfloat16* __restrict__ Blo,
    const float* __restrict__ R, float* __restrict__ Cf,
    __nv_bfloat16* __restrict__ Chi, __nv_bfloat16* __restrict__ Clo,
    int N, int K)
{
    extern __shared__ char smem[];
    uint32_t sb = smem_to_u32(smem);
    int tid = threadIdx.x;
    int wid = tid >> 5, lane = tid & 31;
    int bm = blockIdx.y * 128, bn = blockIdx.x * 128;

    // loader mapping: 4 pieces per tile per thread
    int lr0 = tid >> 3, lc = tid & 7;       // row base, 16B-column
    uint32_t soff[4];
    uint32_t ofsA[4], ofsB[4];
    #pragma unroll
    for (int it = 0; it < 4; it++) {
        int r = lr0 + it * 32;
        soff[it] = TSWZ(r, lc);
        ofsA[it] = (uint32_t)((bm + r) * K + lc * 8);
        ofsB[it] = (uint32_t)((bn + r) * K + lc * 8);
    }

    #define ISSUE(s, kt) do {                                                   \
        uint32_t _b = sb + (uint32_t)(s) * STG;                                 \
        uint32_t _ko = (uint32_t)(kt) * 64;                                     \
        _Pragma("unroll")                                                       \
        for (int _it = 0; _it < 4; _it++) {                                     \
            cpasync16(_b + soff[_it],           Ahi + ofsA[_it] + _ko);         \
            cpasync16(_b + OFF_ALO + soff[_it], Alo + ofsA[_it] + _ko);         \
            cpasync16(_b + OFF_BHI + soff[_it], Bhi + ofsB[_it] + _ko);         \
            cpasync16(_b + OFF_BLO + soff[_it], Blo + ofsB[_it] + _ko);         \
        }                                                                       \
        cpasync_commit();                                                       \
    } while (0)

    float acc[2][8][4];
    #pragma unroll
    for (int ma = 0; ma < 2; ma++)
        #pragma unroll
        for (int na = 0; na < 8; na++)
            #pragma unroll
            for (int j = 0; j < 4; j++) acc[ma][na][j] = 0.f;

    int wm = wid & 3, wn = wid >> 2;
    // precomputed fragment address components
    int arow = wm * 32 + (lane & 15);        // + ma*16
    int ac16 = lane >> 4;                    // + kk*2
    int brow = wn * 64 + (lane & 7) + ((lane >> 4) & 1) * 8;   // + np*16
    int bc16 = (lane >> 3) & 1;              // + kk*2

    const int NC = K >> 6;
    ISSUE(0, 0);

    #pragma unroll 1
    for (int kt = 0; kt < NC; kt++) {
        if (kt + 1 < NC) { ISSUE((kt + 1) & 1, kt + 1); cpasync_wait1(); }
        else             { cpasync_wait0(); }
        __syncthreads();

        uint32_t ab = sb + (uint32_t)(kt & 1) * STG;
        #pragma unroll
        for (int kk = 0; kk < 4; kk++) {
            uint32_t ah[2][4], al[2][4];
            #pragma unroll
            for (int ma = 0; ma < 2; ma++) {
                int r = arow + ma * 16;
                uint32_t ad = ab + TSWZ(r, ac16 + kk * 2);
                ldsm4(ah[ma], ad);
                ldsm4(al[ma], ad + OFF_ALO);
            }
            #pragma unroll
            for (int np = 0; np < 4; np++) {
                int n = brow + np * 16;
                uint32_t bd = ab + OFF_BHI + TSWZ(n, bc16 + kk * 2);
                uint32_t bh[4], bl[4];
                ldsm4(bh, bd);
                ldsm4(bl, bd + 16384);
                #pragma unroll
                for (int ma = 0; ma < 2; ma++) {
                    mma16816(acc[ma][np*2],   ah[ma], bh);
                    mma16816(acc[ma][np*2+1], ah[ma], bh + 2);
                    mma16816(acc[ma][np*2],   ah[ma], bl);
                    mma16816(acc[ma][np*2+1], ah[ma], bl + 2);
                    mma16816(acc[ma][np*2],   al[ma], bh);
                    mma16816(acc[ma][np*2+1], al[ma], bh + 2);
                }
            }
        }
        __syncthreads();
    }

    // epilogue
    int g = lane >> 2, tg = lane & 3;
    #pragma unroll
    for (int ma = 0; ma < 2; ma++) {
        #pragma unroll
        for (int na = 0; na < 8; na++) {
            int row = bm + wm * 32 + ma * 16 + g;
            int col = bn + wn * 64 + na * 8 + tg * 2;
            float* c = acc[ma][na];
            size_t o0 = (size_t)row * N + col;
            size_t o1 = (size_t)(row + 8) * N + col;
            if (EPI == 1) {
                __nv_bfloat16 h0[2], l0[2], h1[2], l1[2];
                split_bf16(fmaxf(c[0], 0.f), h0[0], l0[0]);
                split_bf16(fmaxf(c[1], 0.f), h0[1], l0[1]);
                split_bf16(fmaxf(c[2], 0.f), h1[0], l1[0]);
                split_bf16(fmaxf(c[3], 0.f), h1[1], l1[1]);
                *(uint32_t*)(Chi + o0) = *(uint32_t*)h0;
                *(uint32_t*)(Clo + o0) = *(uint32_t*)l0;
                *(uint32_t*)(Chi + o1) = *(uint32_t*)h1;
                *(uint32_t*)(Clo + o1) = *(uint32_t*)l1;
            } else {
                float2 v0 = make_float2(c[0], c[1]);
                float2 v1 = make_float2(c[2], c[3]);
                if (EPI == 2) {
                    float2 r0 = *(const float2*)(R + o0);
                    float2 r1 = *(const float2*)(R + o1);
                    v0.x += r0.x; v0.y += r0.y;
                    v1.x += r1.x; v1.y += r1.y;
                }
                *(float2*)(Cf + o0) = v0;
                *(float2*)(Cf + o1) = v1;
            }
        }
    }
    #undef ISSUE
}

// ---------------- Flash attention (fp32), writes ctx hi/lo ------------------
__global__ __launch_bounds__(256) void attn_kernel(
    const float* __restrict__ Q, const float* __restrict__ K,
    const float* __restrict__ V, const float* __restrict__ bias,
    __nv_bfloat16* __restrict__ chi, __nv_bfloat16* __restrict__ clo)
{
    __shared__ float QsT[64][64];
    __shared__ float KV [64][64];
    __shared__ float Ps [64][64];

    int qt = blockIdx.x, h = blockIdx.y, b = blockIdx.z;
    int tid = threadIdx.x;
    int tx = tid & 15, ty = tid >> 4;

    #pragma unroll
    for (int it = 0; it < 4; it++) {
        int idx = tid + it * 256;
        int row = idx >> 4, c4 = idx & 15;
        float4 qv = *(const float4*)(Q + (size_t)(b*SS + qt*64 + row) * DD + h*HD + c4*4);
        QsT[c4*4+0][row] = qv.x; QsT[c4*4+1][row] = qv.y;
        QsT[c4*4+2][row] = qv.z; QsT[c4*4+3][row] = qv.w;
    }

    float m[4], l[4], O[4][4];
    #pragma unroll
    for (int i = 0; i < 4; i++) {
        m[i] = -1e30f; l[i] = 0.f;
        #pragma unroll
        for (int j = 0; j < 4; j++) O[i][j] = 0.f;
    }

    for (int kt = 0; kt < SS/64; kt++) {
        #pragma unroll
        for (int it = 0; it < 4; it++) {
            int idx = tid + it * 256;
            int row = idx >> 4, c4 = idx & 15;
            float4 kv = *(const float4*)(K + (size_t)(b*SS + kt*64 + row) * DD + h*HD + c4*4);
            KV[c4*4+0][row] = kv.x; KV[c4*4+1][row] = kv.y;
            KV[c4*4+2][row] = kv.z; KV[c4*4+3][row] = kv.w;
        }
        __syncthreads();

        float s[4][4];
        #pragma unroll
        for (int i = 0; i < 4; i++)
            #pragma unroll
            for (int j = 0; j < 4; j++) s[i][j] = 0.f;
        #pragma unroll
        for (int kk = 0; kk < 64; kk++) {
            float a[4], bb[4];
            #pragma unroll
            for (int i = 0; i < 4; i++) a[i]  = QsT[kk][ty*4 + i];
            #pragma unroll
            for (int j = 0; j < 4; j++) bb[j] = KV [kk][tx*4 + j];
            #pragma unroll
            for (int i = 0; i < 4; i++)
                #pragma unroll
                for (int j = 0; j < 4; j++)
                    s[i][j] = fmaf(a[i], bb[j], s[i][j]);
        }

        #pragma unroll
        for (int i = 0; i < 4; i++) {
            size_t boff = ((size_t)(b*HH + h) * SS + (qt*64 + ty*4 + i)) * SS + kt*64 + tx*4;
            float4 bv = *(const float4*)(bias + boff);
            s[i][0] += bv.x; s[i][1] += bv.y; s[i][2] += bv.z; s[i][3] += bv.w;

            float mt = fmaxf(fmaxf(s[i][0], s[i][1]), fmaxf(s[i][2], s[i][3]));
            #pragma unroll
            for (int off = 8; off; off >>= 1)
                mt = fmaxf(mt, __shfl_xor_sync(0xffffffffu, mt, off, 16));
            float mn = fmaxf(m[i], mt);
            float corr = __expf(m[i] - mn);
            float rs = 0.f;
            #pragma unroll
            for (int j = 0; j < 4; j++) {
                float p = __expf(s[i][j] - mn);
                Ps[ty*4 + i][tx*4 + j] = p;
                rs += p;
            }
            #pragma unroll
            for (int off = 8; off; off >>= 1)
                rs += __shfl_xor_sync(0xffffffffu, rs, off, 16);
            l[i] = l[i] * corr + rs;
            m[i] = mn;
            #pragma unroll
            for (int j = 0; j < 4; j++) O[i][j] *= corr;
        }
        __syncthreads();

        #pragma unroll
        for (int it = 0; it < 4; it++) {
            int idx = tid + it * 256;
            int row = idx >> 4, c4 = idx & 15;
            float4 vv = *(const float4*)(V + (size_t)(b*SS + kt*64 + row) * DD + h*HD + c4*4);
            *(float4*)&KV[row][c4*4] = vv;
        }
        __syncthreads();

        #pragma unroll
        for (int kk = 0; kk < 64; kk++) {
            float a[4], bb[4];
            #pragma unroll
            for (int i = 0; i < 4; i++) a[i]  = Ps[ty*4 + i][kk];
            #pragma unroll
            for (int j = 0; j < 4; j++) bb[j] = KV[kk][tx*4 + j];
            #pragma unroll
            for (int i = 0; i < 4; i++)
                #pragma unroll
                for (int j = 0; j < 4; j++)
                    O[i][j] = fmaf(a[i], bb[j], O[i][j]);
        }
        __syncthreads();
    }

    #pragma unroll
    for (int i = 0; i < 4; i++) {
        float invl = 1.0f / l[i];
        size_t off = (size_t)(b*SS + qt*64 + ty*4 + i) * DD + h*HD + tx*4;
        #pragma unroll
        for (int j = 0; j < 4; j++) {
            __nv_bfloat16 hh, ll;
            split_bf16(O[i][j] * invl, hh, ll);
            chi[off + j] = hh;
            clo[off + j] = ll;
        }
    }
}

// ---------------- launch -----------------------------------------------------
extern "C" void kernel_launch(void* const* d_in, const int* in_sizes, int n_in,
                              void* d_out, int out_size)
{
    const float* Wk   = (const float*)d_in[0];   // primals_1 (D,D)
    const float* Wo   = (const float*)d_in[1];   // primals_2 (D,D)
    const float* Wq   = (const float*)d_in[2];   // primals_3 (D,D)
    const float* Wv   = (const float*)d_in[3];   // primals_4 (D,D)
    const float* ln1  = (const float*)d_in[4];   // primals_5 (D,)
    const float* W1   = (const float*)d_in[5];   // primals_6 (F,D)
    const float* W2   = (const float*)d_in[6];   // primals_7 (D,F)
    const float* ln2  = (const float*)d_in[7];   // primals_8 (D,)
    const float* x    = (const float*)d_in[8];   // primals_9 (B,S,D)
    const float* bias = (const float*)d_in[9];   // primals_10 (B,H,S,S)
    float* out = (float*)d_out;

    #define SYM(p, s) void* p; cudaGetSymbolAddress(&p, s)
    SYM(hhi, g_hhi);  SYM(hlo, g_hlo);
    SYM(pq, g_q);     SYM(pk, g_k);    SYM(pv, g_v);
    SYM(chi, g_chi);  SYM(clo, g_clo);
    SYM(px2, g_x2);
    SYM(h2hi, g_h2hi); SYM(h2lo, g_h2lo);
    SYM(fhi, g_fhi);  SYM(flo, g_flo);
    SYM(wqh, g_wqhi); SYM(wql, g_wqlo);
    SYM(wkh, g_wkhi); SYM(wkl, g_wklo);
    SYM(wvh, g_wvhi); SYM(wvl, g_wvlo);
    SYM(woh, g_wohi); SYM(wol, g_wolo);
    SYM(w1h, g_w1hi); SYM(w1l, g_w1lo);
    SYM(w2h, g_w2hi); SYM(w2l, g_w2lo);
    #undef SYM

    static bool attr_set = false;
    if (!attr_set) {
        cudaFuncSetAttribute(gemm_mma_kernel<0>, cudaFuncAttributeMaxDynamicSharedMemorySize, 2*STG);
        cudaFuncSetAttribute(gemm_mma_kernel<1>, cudaFuncAttributeMaxDynamicSharedMemorySize, 2*STG);
        cudaFuncSetAttribute(gemm_mma_kernel<2>, cudaFuncAttributeMaxDynamicSharedMemorySize, 2*STG);
        attr_set = true;
    }

    typedef const __nv_bfloat16* cbf;
    typedef __nv_bfloat16* bf;

    // weight conversions
    cvt_kernel<<<DD*DD/1024, 256>>>(Wq, (bf)wqh, (bf)wql, DD*DD/4);
    cvt_kernel<<<DD*DD/1024, 256>>>(Wk, (bf)wkh, (bf)wkl, DD*DD/4);
    cvt_kernel<<<DD*DD/1024, 256>>>(Wv, (bf)wvh, (bf)wvl, DD*DD/4);
    cvt_kernel<<<DD*DD/1024, 256>>>(Wo, (bf)woh, (bf)wol, DD*DD/4);
    cvt_kernel<<<FF*DD/1024, 256>>>(W1, (bf)w1h, (bf)w1l, FF*DD/4);
    cvt_kernel<<<DD*FF/1024, 256>>>(W2, (bf)w2h, (bf)w2l, DD*FF/4);

    // 1. h = rmsnorm(x, ln1) -> hi/lo
    rmsnorm_kernel<<<NROWS, 256>>>(x, ln1, (bf)hhi, (bf)hlo);

    // 2-4. q/k/v = h @ W^T (fp32 out)
    dim3 gD(DD/128, NROWS/128);
    gemm_mma_kernel<0><<<gD, 256, 2*STG>>>((cbf)hhi, (cbf)hlo, (cbf)wqh, (cbf)wql,
                                           nullptr, (float*)pq, nullptr, nullptr, DD, DD);
    gemm_mma_kernel<0><<<gD, 256, 2*STG>>>((cbf)hhi, (cbf)hlo, (cbf)wkh, (cbf)wkl,
                                           nullptr, (float*)pk, nullptr, nullptr, DD, DD);
    gemm_mma_kernel<0><<<gD, 256, 2*STG>>>((cbf)hhi, (cbf)hlo, (cbf)wvh, (cbf)wvl,
                                           nullptr, (float*)pv, nullptr, nullptr, DD, DD);

    // 5. attention -> ctx hi/lo
    dim3 ga(SS/64, HH, BB);
    attn_kernel<<<ga, 256>>>((const float*)pq, (const float*)pk, (const float*)pv,
                             bias, (bf)chi, (bf)clo);

    // 6. x2 = x + ctx @ Wo^T (fp32)
    gemm_mma_kernel<2><<<gD, 256, 2*STG>>>((cbf)chi, (cbf)clo, (cbf)woh, (cbf)wol,
                                           x, (float*)px2, nullptr, nullptr, DD, DD);

    // 7. h2 = rmsnorm(x2, ln2) -> hi/lo
    rmsnorm_kernel<<<NROWS, 256>>>((const float*)px2, ln2, (bf)h2hi, (bf)h2lo);

    // 8. ff = relu(h2 @ W1^T) -> hi/lo
    dim3 gF(FF/128, NROWS/128);
    gemm_mma_kernel<1><<<gF, 256, 2*STG>>>((cbf)h2hi, (cbf)h2lo, (cbf)w1h, (cbf)w1l,
                                           nullptr, nullptr, (bf)fhi, (bf)flo, FF, DD);

    // 9. out = x2 + ff @ W2^T (fp32)
    gemm_mma_kernel<2><<<gD, 256, 2*STG>>>((cbf)fhi, (cbf)flo, (cbf)w2h, (cbf)w2l,
                                           (const float*)px2, out, nullptr, nullptr, DD, FF);
}

// round 4
// speedup vs baseline: 3.0216x; 1.5324x over previous
#include <cuda_runtime.h>
#include <cuda_bf16.h>
#include <cstdint>

// Problem constants
#define BB 8
#define SS 1024
#define DD 512
#define HH 8
#define HD 64
#define FF 2048
#define NROWS (BB*SS)          // 8192

// ---------------- helpers ----------------------------------------------------
__device__ __forceinline__ uint32_t smem_to_u32(const void* p) {
    uint32_t a;
    asm("{ .reg .u64 t; cvta.to.shared.u64 t, %1; cvt.u32.u64 %0, t; }"
        : "=r"(a) : "l"(p));
    return a;
}
__device__ __forceinline__ void cpasync16(uint32_t s, const void* g) {
    asm volatile("cp.async.cg.shared.global [%0], [%1], 16;" :: "r"(s), "l"(g));
}
__device__ __forceinline__ void cpasync_commit() {
    asm volatile("cp.async.commit_group;" ::: "memory");
}
__device__ __forceinline__ void cpasync_wait1() {
    asm volatile("cp.async.wait_group 1;" ::: "memory");
}
__device__ __forceinline__ void cpasync_wait0() {
    asm volatile("cp.async.wait_group 0;" ::: "memory");
}
__device__ __forceinline__ void ldsm4(uint32_t* r, uint32_t addr) {
    asm volatile("ldmatrix.sync.aligned.m8n8.x4.shared.b16 {%0,%1,%2,%3}, [%4];"
        : "=r"(r[0]), "=r"(r[1]), "=r"(r[2]), "=r"(r[3]) : "r"(addr));
}
__device__ __forceinline__ void ldsm4t(uint32_t* r, uint32_t addr) {
    asm volatile("ldmatrix.sync.aligned.m8n8.x4.trans.shared.b16 {%0,%1,%2,%3}, [%4];"
        : "=r"(r[0]), "=r"(r[1]), "=r"(r[2]), "=r"(r[3]) : "r"(addr));
}
__device__ __forceinline__ void mma16816(float* c, const uint32_t* a, const uint32_t* b) {
    asm volatile(
        "mma.sync.aligned.m16n8k16.row.col.f32.bf16.bf16.f32 "
        "{%0,%1,%2,%3}, {%4,%5,%6,%7}, {%8,%9}, {%0,%1,%2,%3};"
        : "+f"(c[0]), "+f"(c[1]), "+f"(c[2]), "+f"(c[3])
        : "r"(a[0]), "r"(a[1]), "r"(a[2]), "r"(a[3]), "r"(b[0]), "r"(b[1]));
}
__device__ __forceinline__ void split_bf16(float v, __nv_bfloat16& h, __nv_bfloat16& l) {
    h = __float2bfloat16_rn(v);
    l = __float2bfloat16_rn(v - __bfloat162float(h));
}
__device__ __forceinline__ void split2f(float v, float& hf, float& lf) {
    __nv_bfloat16 h = __float2bfloat16_rn(v);
    hf = __bfloat162float(h);
    lf = v - hf;
}
// pack two floats to bf16x2: x0 -> low half, x1 -> high half
__device__ __forceinline__ uint32_t packbf(float x0, float x1) {
    uint32_t r;
    asm("cvt.rn.bf16x2.f32 %0, %1, %2;" : "=r"(r) : "f"(x1), "f"(x0));
    return r;
}

// ---------------- scratch (device globals) ----------------------------------
__device__ __nv_bfloat16 g_hhi [NROWS*DD], g_hlo [NROWS*DD];
__device__ __nv_bfloat16 g_qhi [NROWS*DD], g_qlo [NROWS*DD];
__device__ __nv_bfloat16 g_khi [NROWS*DD], g_klo [NROWS*DD];
__device__ __nv_bfloat16 g_vhi [NROWS*DD], g_vlo [NROWS*DD];
__device__ __nv_bfloat16 g_chi [NROWS*DD], g_clo [NROWS*DD];
__device__ float         g_x2  [NROWS*DD];
__device__ __nv_bfloat16 g_h2hi[NROWS*DD], g_h2lo[NROWS*DD];
__device__ __nv_bfloat16 g_fhi [NROWS*FF], g_flo [NROWS*FF];
__device__ __nv_bfloat16 g_wqhi[DD*DD], g_wqlo[DD*DD];
__device__ __nv_bfloat16 g_wkhi[DD*DD], g_wklo[DD*DD];
__device__ __nv_bfloat16 g_wvhi[DD*DD], g_wvlo[DD*DD];
__device__ __nv_bfloat16 g_wohi[DD*DD], g_wolo[DD*DD];
__device__ __nv_bfloat16 g_w1hi[FF*DD], g_w1lo[FF*DD];
__device__ __nv_bfloat16 g_w2hi[DD*FF], g_w2lo[DD*FF];

// ---------------- fp32 -> (hi, lo) bf16 conversion --------------------------
__global__ __launch_bounds__(256) void cvt_kernel(
    const float* __restrict__ x, __nv_bfloat16* __restrict__ hi,
    __nv_bfloat16* __restrict__ lo, int n4)
{
    int i = blockIdx.x * 256 + threadIdx.x;
    if (i >= n4) return;
    float4 v = ((const float4*)x)[i];
    __nv_bfloat16 h[4], l[4];
    split_bf16(v.x, h[0], l[0]); split_bf16(v.y, h[1], l[1]);
    split_bf16(v.z, h[2], l[2]); split_bf16(v.w, h[3], l[3]);
    *(uint2*)(hi + (size_t)i * 4) = *(uint2*)h;
    *(uint2*)(lo + (size_t)i * 4) = *(uint2*)l;
}

// ---------------- RMSNorm: writes hi/lo bf16 ---------------------------------
__global__ __launch_bounds__(256) void rmsnorm_kernel(
    const float* __restrict__ x, const float* __restrict__ w,
    __nv_bfloat16* __restrict__ ohi, __nv_bfloat16* __restrict__ olo)
{
    int row = blockIdx.x;
    const float* xr = x + (size_t)row * DD;
    int t = threadIdx.x;
    float v0 = xr[t];
    float v1 = xr[t + 256];
    float ss = v0 * v0 + v1 * v1;
    #pragma unroll
    for (int off = 16; off; off >>= 1)
        ss += __shfl_xor_sync(0xffffffffu, ss, off);
    __shared__ float red[8];
    if ((t & 31) == 0) red[t >> 5] = ss;
    __syncthreads();
    float total = 0.f;
    #pragma unroll
    for (int i = 0; i < 8; i++) total += red[i];
    float inv = rsqrtf(total * (1.0f / DD) + 1e-6f);
    float o0 = w[t] * v0 * inv;
    float o1 = w[t + 256] * v1 * inv;
    __nv_bfloat16 h, l;
    size_t base = (size_t)row * DD;
    split_bf16(o0, h, l); ohi[base + t] = h;       olo[base + t] = l;
    split_bf16(o1, h, l); ohi[base + t + 256] = h; olo[base + t + 256] = l;
}

// ---------------- split-bf16 tensor-core GEMM (mma.sync) ---------------------
// C[M,N] = epi( A[M,K] @ B[N,K]^T (+R) ), A/B given as bf16 hi/lo pairs.
// EPI: 1 = relu -> bf16 hi/lo   2 = +R -> fp32   3 = bf16 hi/lo (no relu)
#define STG 65536
#define OFF_ALO 16384
#define OFF_BHI 32768
#define OFF_BLO 49152
// swizzled byte offset within a [rows x 64 bf16] tile (128B rows)
#define TSWZ(r, c16) ((uint32_t)((r) * 128 + (((c16) ^ ((r) & 7)) << 4)))

template <int EPI>
__global__ __launch_bounds__(256) void gemm_mma_kernel(
    const __nv_bfloat16* __restrict__ Ahi, const __nv_bfloat16* __restrict__ Alo,
    const __nv_bfloat16* __restrict__ Bhi, const __nv_bfloat16* __restrict__ Blo,
    const float* __restrict__ R, float* __restrict__ Cf,
    __nv_bfloat16* __restrict__ Chi, __nv_bfloat16* __restrict__ Clo,
    int N, int K)
{
    extern __shared__ char smem[];
    uint32_t sb = smem_to_u32(smem);
    int tid = threadIdx.x;
    int wid = tid >> 5, lane = tid & 31;
    int bm = blockIdx.y * 128, bn = blockIdx.x * 128;

    int lr0 = tid >> 3, lc = tid & 7;
    uint32_t soff[4];
    uint32_t ofsA[4], ofsB[4];
    #pragma unroll
    for (int it = 0; it < 4; it++) {
        int r = lr0 + it * 32;
        soff[it] = TSWZ(r, lc);
        ofsA[it] = (uint32_t)((bm + r) * K + lc * 8);
        ofsB[it] = (uint32_t)((bn + r) * K + lc * 8);
    }

    #define ISSUE(s, kt) do {                                                   \
        uint32_t _b = sb + (uint32_t)(s) * STG;                                 \
        uint32_t _ko = (uint32_t)(kt) * 64;                                     \
        _Pragma("unroll")                                                       \
        for (int _it = 0; _it < 4; _it++) {                                     \
            cpasync16(_b + soff[_it],           Ahi + ofsA[_it] + _ko);         \
            cpasync16(_b + OFF_ALO + soff[_it], Alo + ofsA[_it] + _ko);         \
            cpasync16(_b + OFF_BHI + soff[_it], Bhi + ofsB[_it] + _ko);         \
            cpasync16(_b + OFF_BLO + soff[_it], Blo + ofsB[_it] + _ko);         \
        }                                                                       \
        cpasync_commit();                                                       \
    } while (0)

    float acc[2][8][4];
    #pragma unroll
    for (int ma = 0; ma < 2; ma++)
        #pragma unroll
        for (int na = 0; na < 8; na++)
            #pragma unroll
            for (int j = 0; j < 4; j++) acc[ma][na][j] = 0.f;

    int wm = wid & 3, wn = wid >> 2;
    int arow = wm * 32 + (lane & 15);
    int ac16 = lane >> 4;
    int brow = wn * 64 + (lane & 7) + ((lane >> 4) & 1) * 8;
    int bc16 = (lane >> 3) & 1;

    const int NC = K >> 6;
    ISSUE(0, 0);

    #pragma unroll 1
    for (int kt = 0; kt < NC; kt++) {
        if (kt + 1 < NC) { ISSUE((kt + 1) & 1, kt + 1); cpasync_wait1(); }
        else             { cpasync_wait0(); }
        __syncthreads();

        uint32_t ab = sb + (uint32_t)(kt & 1) * STG;
        #pragma unroll
        for (int kk = 0; kk < 4; kk++) {
            uint32_t ah[2][4], al[2][4];
            #pragma unroll
            for (int ma = 0; ma < 2; ma++) {
                int r = arow + ma * 16;
                uint32_t ad = ab + TSWZ(r, ac16 + kk * 2);
                ldsm4(ah[ma], ad);
                ldsm4(al[ma], ad + OFF_ALO);
            }
            #pragma unroll
            for (int np = 0; np < 4; np++) {
                int n = brow + np * 16;
                uint32_t bd = ab + OFF_BHI + TSWZ(n, bc16 + kk * 2);
                uint32_t bh[4], bl[4];
                ldsm4(bh, bd);
                ldsm4(bl, bd + 16384);
                #pragma unroll
                for (int ma = 0; ma < 2; ma++) {
                    mma16816(acc[ma][np*2],   ah[ma], bh);
                    mma16816(acc[ma][np*2+1], ah[ma], bh + 2);
                    mma16816(acc[ma][np*2],   ah[ma], bl);
                    mma16816(acc[ma][np*2+1], ah[ma], bl + 2);
                    mma16816(acc[ma][np*2],   al[ma], bh);
                    mma16816(acc[ma][np*2+1], al[ma], bh + 2);
                }
            }
        }
        __syncthreads();
    }

    // epilogue
    int g = lane >> 2, tg = lane & 3;
    #pragma unroll
    for (int ma = 0; ma < 2; ma++) {
        #pragma unroll
        for (int na = 0; na < 8; na++) {
            int row = bm + wm * 32 + ma * 16 + g;
            int col = bn + wn * 64 + na * 8 + tg * 2;
            float* c = acc[ma][na];
            size_t o0 = (size_t)row * N + col;
            size_t o1 = (size_t)(row + 8) * N + col;
            if (EPI == 1 || EPI == 3) {
                float v0 = c[0], v1 = c[1], v2 = c[2], v3 = c[3];
                if (EPI == 1) {
                    v0 = fmaxf(v0, 0.f); v1 = fmaxf(v1, 0.f);
                    v2 = fmaxf(v2, 0.f); v3 = fmaxf(v3, 0.f);
                }
                __nv_bfloat16 h0[2], l0[2], h1[2], l1[2];
                split_bf16(v0, h0[0], l0[0]); split_bf16(v1, h0[1], l0[1]);
                split_bf16(v2, h1[0], l1[0]); split_bf16(v3, h1[1], l1[1]);
                *(uint32_t*)(Chi + o0) = *(uint32_t*)h0;
                *(uint32_t*)(Clo + o0) = *(uint32_t*)l0;
                *(uint32_t*)(Chi + o1) = *(uint32_t*)h1;
                *(uint32_t*)(Clo + o1) = *(uint32_t*)l1;
            } else {
                float2 v0 = make_float2(c[0], c[1]);
                float2 v1 = make_float2(c[2], c[3]);
                if (EPI == 2) {
                    float2 r0 = *(const float2*)(R + o0);
                    float2 r1 = *(const float2*)(R + o1);
                    v0.x += r0.x; v0.y += r0.y;
                    v1.x += r1.x; v1.y += r1.y;
                }
                *(float2*)(Cf + o0) = v0;
                *(float2*)(Cf + o1) = v1;
            }
        }
    }
    #undef ISSUE
}

// ---------------- tensor-core flash attention --------------------------------
// grid (S/128, H, B), 256 threads (8 warps x 16 query rows).
// Key tiles of 64, double-buffered via cp.async. All operands split bf16.
// SMEM: Qhi 16K | Qlo 16K | 2 stages x (Khi 8K | Klo 8K | Vhi 8K | Vlo 8K)
#define AQ_HI 0u
#define AQ_LO 16384u
#define AKV0  32768u
#define AKV_STG 32768u
#define A_SMEM (32768u + 2u*32768u)

__global__ __launch_bounds__(256) void attn_mma_kernel(
    const __nv_bfloat16* __restrict__ Qhi, const __nv_bfloat16* __restrict__ Qlo,
    const __nv_bfloat16* __restrict__ Khi, const __nv_bfloat16* __restrict__ Klo,
    const __nv_bfloat16* __restrict__ Vhi, const __nv_bfloat16* __restrict__ Vlo,
    const float* __restrict__ bias,
    __nv_bfloat16* __restrict__ chi, __nv_bfloat16* __restrict__ clo)
{
    extern __shared__ char smem[];
    uint32_t sb = smem_to_u32(smem);
    int tid = threadIdx.x, wid = tid >> 5, lane = tid & 31;
    int qt = blockIdx.x, h = blockIdx.y, b = blockIdx.z;

    // ---- Q load (group 0) ----
    {
        int r = tid >> 1;
        int cb = (tid & 1) * 4;
        size_t grow = ((size_t)(b * SS + qt * 128 + r)) * DD + h * HD;
        #pragma unroll
        for (int i = 0; i < 4; i++) {
            int c16 = cb + i;
            uint32_t so = TSWZ(r, c16);
            cpasync16(sb + AQ_HI + so, Qhi + grow + c16 * 8);
            cpasync16(sb + AQ_LO + so, Qlo + grow + c16 * 8);
        }
        cpasync_commit();
    }
    // ---- KV tile issue ----
    int kvr = tid & 63;
    int kvcb = (tid >> 6) * 2;
    #define ISSUE_KV(kt, stg) do {                                              \
        uint32_t _bse = sb + AKV0 + (uint32_t)(stg) * AKV_STG;                  \
        size_t _gr = ((size_t)(b * SS + (kt) * 64 + kvr)) * DD + h * HD;        \
        _Pragma("unroll")                                                       \
        for (int _i = 0; _i < 2; _i++) {                                        \
            int _c = kvcb + _i;                                                 \
            uint32_t _so = TSWZ(kvr, _c);                                       \
            cpasync16(_bse + _so,          Khi + _gr + _c * 8);                 \
            cpasync16(_bse + 8192 + _so,   Klo + _gr + _c * 8);                 \
            cpasync16(_bse + 16384 + _so,  Vhi + _gr + _c * 8);                 \
            cpasync16(_bse + 24576 + _so,  Vlo + _gr + _c * 8);                 \
        }                                                                       \
        cpasync_commit();                                                       \
    } while (0)

    ISSUE_KV(0, 0);

    float oacc[8][4];
    #pragma unroll
    for (int na = 0; na < 8; na++)
        #pragma unroll
        for (int j = 0; j < 4; j++) oacc[na][j] = 0.f;
    float m0 = -1e30f, m1 = -1e30f, l0 = 0.f, l1 = 0.f;

    int arow = wid * 16 + (lane & 15);
    int ac16 = lane >> 4;
    int bro  = (lane & 7) + ((lane >> 4) & 1) * 8;
    int bc16 = (lane >> 3) & 1;
    int vro  = lane & 15;
    int vch  = lane >> 4;

    size_t brow0 = ((size_t)(b * HH + h) * SS + (qt * 128 + wid * 16 + (lane >> 2))) * SS
                   + 2 * (lane & 3);
    size_t brow1 = brow0 + 8 * (size_t)SS;

    #pragma unroll 1
    for (int kt = 0; kt < 16; kt++) {
        if (kt + 1 < 16) { ISSUE_KV(kt + 1, (kt + 1) & 1); cpasync_wait1(); }
        else             { cpasync_wait0(); }
        __syncthreads();
        uint32_t kvb = sb + AKV0 + (uint32_t)(kt & 1) * AKV_STG;

        // ---- S = Q K^T (split: 3 terms) ----
        float sacc[8][4];
        #pragma unroll
        for (int na = 0; na < 8; na++)
            #pragma unroll
            for (int j = 0; j < 4; j++) sacc[na][j] = 0.f;
        #pragma unroll
        for (int kk = 0; kk < 4; kk++) {
            uint32_t ah[4], al[4];
            uint32_t ad = sb + AQ_HI + TSWZ(arow, ac16 + kk * 2);
            ldsm4(ah, ad);
            ldsm4(al, ad + AQ_LO);
            #pragma unroll
            for (int ng = 0; ng < 4; ng++) {
                uint32_t bd = kvb + TSWZ(bro + ng * 16, bc16 + kk * 2);
                uint32_t kh[4], kl[4];
                ldsm4(kh, bd);
                ldsm4(kl, bd + 8192);
                mma16816(sacc[ng*2],   ah, kh);
                mma16816(sacc[ng*2+1], ah, kh + 2);
                mma16816(sacc[ng*2],   ah, kl);
                mma16816(sacc[ng*2+1], ah, kl + 2);
                mma16816(sacc[ng*2],   al, kh);
                mma16816(sacc[ng*2+1], al, kh + 2);
            }
        }

        // ---- bias + online softmax ----
        const float* bp0 = bias + brow0 + kt * 64;
        const float* bp1 = bias + brow1 + kt * 64;
        float tm0 = -1e30f, tm1 = -1e30f;
        #pragma unroll
        for (int na = 0; na < 8; na++) {
            float2 bv0 = *(const float2*)(bp0 + na * 8);
            float2 bv1 = *(const float2*)(bp1 + na * 8);
            sacc[na][0] += bv0.x; sacc[na][1] += bv0.y;
            sacc[na][2] += bv1.x; sacc[na][3] += bv1.y;
            tm0 = fmaxf(tm0, fmaxf(sacc[na][0], sacc[na][1]));
            tm1 = fmaxf(tm1, fmaxf(sacc[na][2], sacc[na][3]));
        }
        tm0 = fmaxf(tm0, __shfl_xor_sync(0xffffffffu, tm0, 1));
        tm0 = fmaxf(tm0, __shfl_xor_sync(0xffffffffu, tm0, 2));
        tm1 = fmaxf(tm1, __shfl_xor_sync(0xffffffffu, tm1, 1));
        tm1 = fmaxf(tm1, __shfl_xor_sync(0xffffffffu, tm1, 2));
        float mn0 = fmaxf(m0, tm0), mn1 = fmaxf(m1, tm1);
        float c0 = __expf(m0 - mn0), c1 = __expf(m1 - mn1);
        float s0 = 0.f, s1 = 0.f;
        #pragma unroll
        for (int na = 0; na < 8; na++) {
            float p0 = __expf(sacc[na][0] - mn0);
            float p1 = __expf(sacc[na][1] - mn0);
            float p2 = __expf(sacc[na][2] - mn1);
            float p3 = __expf(sacc[na][3] - mn1);
            sacc[na][0] = p0; sacc[na][1] = p1;
            sacc[na][2] = p2; sacc[na][3] = p3;
            s0 += p0 + p1; s1 += p2 + p3;
        }
        s0 += __shfl_xor_sync(0xffffffffu, s0, 1);
        s0 += __shfl_xor_sync(0xffffffffu, s0, 2);
        s1 += __shfl_xor_sync(0xffffffffu, s1, 1);
        s1 += __shfl_xor_sync(0xffffffffu, s1, 2);
        l0 = l0 * c0 + s0; l1 = l1 * c1 + s1;
        m0 = mn0; m1 = mn1;
        #pragma unroll
        for (int na = 0; na < 8; na++) {
            oacc[na][0] *= c0; oacc[na][1] *= c0;
            oacc[na][2] *= c1; oacc[na][3] *= c1;
        }

        // ---- O += P V (split: 3 terms); P frags built from S accum regs ----
        #pragma unroll
        for (int kk = 0; kk < 4; kk++) {
            uint32_t ph[4], pl[4];
            {
                float h00, l00, h01, l01;
                split2f(sacc[2*kk][0], h00, l00); split2f(sacc[2*kk][1], h01, l01);
                ph[0] = packbf(h00, h01); pl[0] = packbf(l00, l01);
                split2f(sacc[2*kk][2], h00, l00); split2f(sacc[2*kk][3], h01, l01);
                ph[1] = packbf(h00, h01); pl[1] = packbf(l00, l01);
                split2f(sacc[2*kk+1][0], h00, l00); split2f(sacc[2*kk+1][1], h01, l01);
                ph[2] = packbf(h00, h01); pl[2] = packbf(l00, l01);
                split2f(sacc[2*kk+1][2], h00, l00); split2f(sacc[2*kk+1][3], h01, l01);
                ph[3] = packbf(h00, h01); pl[3] = packbf(l00, l01);
            }
            #pragma unroll
            for (int j = 0; j < 4; j++) {
                uint32_t vd = kvb + 16384 + TSWZ(kk * 16 + vro, 2 * j + vch);
                uint32_t vh[4], vl[4];
                ldsm4t(vh, vd);
                ldsm4t(vl, vd + 8192);
                mma16816(oacc[j*2],   ph, vh);
                mma16816(oacc[j*2+1], ph, vh + 2);
                mma16816(oacc[j*2],   ph, vl);
                mma16816(oacc[j*2+1], ph, vl + 2);
                mma16816(oacc[j*2],   pl, vh);
                mma16816(oacc[j*2+1], pl, vh + 2);
            }
        }
        __syncthreads();
    }

    // ---- epilogue: ctx = O / l, write hi/lo ----
    float il0 = 1.0f / l0, il1 = 1.0f / l1;
    int row0 = b * SS + qt * 128 + wid * 16 + (lane >> 2);
    int colb = h * HD + 2 * (lane & 3);
    #pragma unroll
    for (int na = 0; na < 8; na++) {
        size_t o0 = (size_t)row0 * DD + colb + na * 8;
        size_t o1 = o0 + 8 * (size_t)DD;
        __nv_bfloat16 hh[2], ll[2];
        split_bf16(oacc[na][0] * il0, hh[0], ll[0]);
        split_bf16(oacc[na][1] * il0, hh[1], ll[1]);
        *(uint32_t*)(chi + o0) = *(uint32_t*)hh;
        *(uint32_t*)(clo + o0) = *(uint32_t*)ll;
        split_bf16(oacc[na][2] * il1, hh[0], ll[0]);
        split_bf16(oacc[na][3] * il1, hh[1], ll[1]);
        *(uint32_t*)(chi + o1) = *(uint32_t*)hh;
        *(uint32_t*)(clo + o1) = *(uint32_t*)ll;
    }
    #undef ISSUE_KV
}

// ---------------- launch -----------------------------------------------------
extern "C" void kernel_launch(void* const* d_in, const int* in_sizes, int n_in,
                              void* d_out, int out_size)
{
    const float* Wk   = (const float*)d_in[0];
    const float* Wo   = (const float*)d_in[1];
    const float* Wq   = (const float*)d_in[2];
    const float* Wv   = (const float*)d_in[3];
    const float* ln1  = (const float*)d_in[4];
    const float* W1   = (const float*)d_in[5];
    const float* W2   = (const float*)d_in[6];
    const float* ln2  = (const float*)d_in[7];
    const float* x    = (const float*)d_in[8];
    const float* bias = (const float*)d_in[9];
    float* out = (float*)d_out;

    #define SYM(p, s) void* p; cudaGetSymbolAddress(&p, s)
    SYM(hhi, g_hhi);  SYM(hlo, g_hlo);
    SYM(qhi, g_qhi);  SYM(qlo, g_qlo);
    SYM(khi, g_khi);  SYM(klo, g_klo);
    SYM(vhi, g_vhi);  SYM(vlo, g_vlo);
    SYM(chi, g_chi);  SYM(clo, g_clo);
    SYM(px2, g_x2);
    SYM(h2hi, g_h2hi); SYM(h2lo, g_h2lo);
    SYM(fhi, g_fhi);  SYM(flo, g_flo);
    SYM(wqh, g_wqhi); SYM(wql, g_wqlo);
    SYM(wkh, g_wkhi); SYM(wkl, g_wklo);
    SYM(wvh, g_wvhi); SYM(wvl, g_wvlo);
    SYM(woh, g_wohi); SYM(wol, g_wolo);
    SYM(w1h, g_w1hi); SYM(w1l, g_w1lo);
    SYM(w2h, g_w2hi); SYM(w2l, g_w2lo);
    #undef SYM

    static bool attr_set = false;
    if (!attr_set) {
        cudaFuncSetAttribute(gemm_mma_kernel<1>, cudaFuncAttributeMaxDynamicSharedMemorySize, 2*STG);
        cudaFuncSetAttribute(gemm_mma_kernel<2>, cudaFuncAttributeMaxDynamicSharedMemorySize, 2*STG);
        cudaFuncSetAttribute(gemm_mma_kernel<3>, cudaFuncAttributeMaxDynamicSharedMemorySize, 2*STG);
        cudaFuncSetAttribute(attn_mma_kernel, cudaFuncAttributeMaxDynamicSharedMemorySize, A_SMEM);
        attr_set = true;
    }

    typedef const __nv_bfloat16* cbf;
    typedef __nv_bfloat16* bf;

    // weight conversions
    cvt_kernel<<<DD*DD/1024, 256>>>(Wq, (bf)wqh, (bf)wql, DD*DD/4);
    cvt_kernel<<<DD*DD/1024, 256>>>(Wk, (bf)wkh, (bf)wkl, DD*DD/4);
    cvt_kernel<<<DD*DD/1024, 256>>>(Wv, (bf)wvh, (bf)wvl, DD*DD/4);
    cvt_kernel<<<DD*DD/1024, 256>>>(Wo, (bf)woh, (bf)wol, DD*DD/4);
    cvt_kernel<<<FF*DD/1024, 256>>>(W1, (bf)w1h, (bf)w1l, FF*DD/4);
    cvt_kernel<<<DD*FF/1024, 256>>>(W2, (bf)w2h, (bf)w2l, DD*FF/4);

    // 1. h = rmsnorm(x, ln1) -> hi/lo
    rmsnorm_kernel<<<NROWS, 256>>>(x, ln1, (bf)hhi, (bf)hlo);

    // 2-4. q/k/v = h @ W^T -> bf16 hi/lo
    dim3 gD(DD/128, NROWS/128);
    gemm_mma_kernel<3><<<gD, 256, 2*STG>>>((cbf)hhi, (cbf)hlo, (cbf)wqh, (cbf)wql,
                                           nullptr, nullptr, (bf)qhi, (bf)qlo, DD, DD);
    gemm_mma_kernel<3><<<gD, 256, 2*STG>>>((cbf)hhi, (cbf)hlo, (cbf)wkh, (cbf)wkl,
                                           nullptr, nullptr, (bf)khi, (bf)klo, DD, DD);
    gemm_mma_kernel<3><<<gD, 256, 2*STG>>>((cbf)hhi, (cbf)hlo, (cbf)wvh, (cbf)wvl,
                                           nullptr, nullptr, (bf)vhi, (bf)vlo, DD, DD);

    // 5. attention -> ctx hi/lo
    dim3 ga(SS/128, HH, BB);
    attn_mma_kernel<<<ga, 256, A_SMEM>>>((cbf)qhi, (cbf)qlo, (cbf)khi, (cbf)klo,
                                         (cbf)vhi, (cbf)vlo, bias, (bf)chi, (bf)clo);

    // 6. x2 = x + ctx @ Wo^T (fp32)
    gemm_mma_kernel<2><<<gD, 256, 2*STG>>>((cbf)chi, (cbf)clo, (cbf)woh, (cbf)wol,
                                           x, (float*)px2, nullptr, nullptr, DD, DD);

    // 7. h2 = rmsnorm(x2, ln2) -> hi/lo
    rmsnorm_kernel<<<NROWS, 256>>>((const float*)px2, ln2, (bf)h2hi, (bf)h2lo);

    // 8. ff = relu(h2 @ W1^T) -> hi/lo
    dim3 gF(FF/128, NROWS/128);
    gemm_mma_kernel<1><<<gF, 256, 2*STG>>>((cbf)h2hi, (cbf)h2lo, (cbf)w1h, (cbf)w1l,
                                           nullptr, nullptr, (bf)fhi, (bf)flo, FF, DD);

    // 9. out = x2 + ff @ W2^T (fp32)
    gemm_mma_kernel<2><<<gD, 256, 2*STG>>>((cbf)fhi, (cbf)flo, (cbf)w2h, (cbf)w2l,
                                           (const float*)px2, out, nullptr, nullptr, DD, FF);
}

// round 5
// speedup vs baseline: 3.1126x; 1.0301x over previous
#include <cuda_runtime.h>
#include <cuda_bf16.h>
#include <cuda_fp16.h>
#include <cstdint>

// Problem constants
#define BB 8
#define SS 1024
#define DD 512
#define HH 8
#define HD 64
#define FF 2048
#define NROWS (BB*SS)          // 8192
#define L2E 1.4426950408889634f

// ---------------- helpers ----------------------------------------------------
__device__ __forceinline__ uint32_t smem_to_u32(const void* p) {
    uint32_t a;
    asm("{ .reg .u64 t; cvta.to.shared.u64 t, %1; cvt.u32.u64 %0, t; }"
        : "=r"(a) : "l"(p));
    return a;
}
__device__ __forceinline__ void cpasync16(uint32_t s, const void* g) {
    asm volatile("cp.async.cg.shared.global [%0], [%1], 16;" :: "r"(s), "l"(g));
}
__device__ __forceinline__ void cpasync_commit() {
    asm volatile("cp.async.commit_group;" ::: "memory");
}
__device__ __forceinline__ void cpasync_wait1() {
    asm volatile("cp.async.wait_group 1;" ::: "memory");
}
__device__ __forceinline__ void cpasync_wait0() {
    asm volatile("cp.async.wait_group 0;" ::: "memory");
}
__device__ __forceinline__ void ldsm4(uint32_t* r, uint32_t addr) {
    asm volatile("ldmatrix.sync.aligned.m8n8.x4.shared.b16 {%0,%1,%2,%3}, [%4];"
        : "=r"(r[0]), "=r"(r[1]), "=r"(r[2]), "=r"(r[3]) : "r"(addr));
}
__device__ __forceinline__ void ldsm4t(uint32_t* r, uint32_t addr) {
    asm volatile("ldmatrix.sync.aligned.m8n8.x4.trans.shared.b16 {%0,%1,%2,%3}, [%4];"
        : "=r"(r[0]), "=r"(r[1]), "=r"(r[2]), "=r"(r[3]) : "r"(addr));
}
__device__ __forceinline__ void mma16816(float* c, const uint32_t* a, const uint32_t* b) {
    asm volatile(
        "mma.sync.aligned.m16n8k16.row.col.f32.bf16.bf16.f32 "
        "{%0,%1,%2,%3}, {%4,%5,%6,%7}, {%8,%9}, {%0,%1,%2,%3};"
        : "+f"(c[0]), "+f"(c[1]), "+f"(c[2]), "+f"(c[3])
        : "r"(a[0]), "r"(a[1]), "r"(a[2]), "r"(a[3]), "r"(b[0]), "r"(b[1]));
}
__device__ __forceinline__ void mma16816h(float* c, const uint32_t* a, const uint32_t* b) {
    asm volatile(
        "mma.sync.aligned.m16n8k16.row.col.f32.f16.f16.f32 "
        "{%0,%1,%2,%3}, {%4,%5,%6,%7}, {%8,%9}, {%0,%1,%2,%3};"
        : "+f"(c[0]), "+f"(c[1]), "+f"(c[2]), "+f"(c[3])
        : "r"(a[0]), "r"(a[1]), "r"(a[2]), "r"(a[3]), "r"(b[0]), "r"(b[1]));
}
__device__ __forceinline__ void split_bf16(float v, __nv_bfloat16& h, __nv_bfloat16& l) {
    h = __float2bfloat16_rn(v);
    l = __float2bfloat16_rn(v - __bfloat162float(h));
}
__device__ __forceinline__ void split_f16(float v, __half& h, __half& l) {
    h = __float2half_rn(v);
    l = __float2half_rn(v - __half2float(h));
}
// pack two floats to f16x2: x0 -> low half, x1 -> high half
__device__ __forceinline__ uint32_t packh(float x0, float x1) {
    uint32_t r;
    asm("cvt.rn.f16x2.f32 %0, %1, %2;" : "=r"(r) : "f"(x1), "f"(x0));
    return r;
}
__device__ __forceinline__ uint32_t ex2h2(uint32_t v) {
    uint32_t r;
    asm("ex2.approx.f16x2 %0, %1;" : "=r"(r) : "r"(v));
    return r;
}
__device__ __forceinline__ float ex2f(float x) {
    float r;
    asm("ex2.approx.f32 %0, %1;" : "=f"(r) : "f"(x));
    return r;
}

// ---------------- scratch (device globals) ----------------------------------
__device__ __nv_bfloat16 g_hhi [NROWS*DD], g_hlo [NROWS*DD];
__device__ __nv_bfloat16 g_qhi [NROWS*DD], g_qlo [NROWS*DD];
__device__ __nv_bfloat16 g_khi [NROWS*DD], g_klo [NROWS*DD];
__device__ __half        g_vhi [NROWS*DD], g_vlo [NROWS*DD];
__device__ __nv_bfloat16 g_chi [NROWS*DD], g_clo [NROWS*DD];
__device__ float         g_x2  [NROWS*DD];
__device__ __nv_bfloat16 g_h2hi[NROWS*DD], g_h2lo[NROWS*DD];
__device__ __nv_bfloat16 g_fhi [NROWS*FF], g_flo [NROWS*FF];
__device__ __nv_bfloat16 g_wqhi[DD*DD], g_wqlo[DD*DD];
__device__ __nv_bfloat16 g_wkhi[DD*DD], g_wklo[DD*DD];
__device__ __nv_bfloat16 g_wvhi[DD*DD], g_wvlo[DD*DD];
__device__ __nv_bfloat16 g_wohi[DD*DD], g_wolo[DD*DD];
__device__ __nv_bfloat16 g_w1hi[FF*DD], g_w1lo[FF*DD];
__device__ __nv_bfloat16 g_w2hi[DD*FF], g_w2lo[DD*FF];

// ---------------- fused fp32 -> (hi, lo) conversion for 6 weights ------------
struct CvtArgs {
    const float* s[6];
    __nv_bfloat16* h[6];
    __nv_bfloat16* l[6];
    int n4[6];
};
__global__ __launch_bounds__(256) void cvt6_kernel(CvtArgs a)
{
    int w = blockIdx.y;
    int i = blockIdx.x * 256 + threadIdx.x;
    if (i >= a.n4[w]) return;
    float4 v = ((const float4*)a.s[w])[i];
    __nv_bfloat16 h[4], l[4];
    split_bf16(v.x, h[0], l[0]); split_bf16(v.y, h[1], l[1]);
    split_bf16(v.z, h[2], l[2]); split_bf16(v.w, h[3], l[3]);
    *(uint2*)(a.h[w] + (size_t)i * 4) = *(uint2*)h;
    *(uint2*)(a.l[w] + (size_t)i * 4) = *(uint2*)l;
}

// ---------------- RMSNorm: writes hi/lo bf16 ---------------------------------
__global__ __launch_bounds__(256) void rmsnorm_kernel(
    const float* __restrict__ x, const float* __restrict__ w,
    __nv_bfloat16* __restrict__ ohi, __nv_bfloat16* __restrict__ olo)
{
    int row = blockIdx.x;
    const float* xr = x + (size_t)row * DD;
    int t = threadIdx.x;
    float v0 = xr[t];
    float v1 = xr[t + 256];
    float ss = v0 * v0 + v1 * v1;
    #pragma unroll
    for (int off = 16; off; off >>= 1)
        ss += __shfl_xor_sync(0xffffffffu, ss, off);
    __shared__ float red[8];
    if ((t & 31) == 0) red[t >> 5] = ss;
    __syncthreads();
    float total = 0.f;
    #pragma unroll
    for (int i = 0; i < 8; i++) total += red[i];
    float inv = rsqrtf(total * (1.0f / DD) + 1e-6f);
    float o0 = w[t] * v0 * inv;
    float o1 = w[t + 256] * v1 * inv;
    __nv_bfloat16 h, l;
    size_t base = (size_t)row * DD;
    split_bf16(o0, h, l); ohi[base + t] = h;       olo[base + t] = l;
    split_bf16(o1, h, l); ohi[base + t + 256] = h; olo[base + t + 256] = l;
}

// ---------------- split-bf16 tensor-core GEMM (mma.sync) ---------------------
// C[M,N] = epi( A[M,K] @ B[N,K]^T (+R) ), A/B given as bf16 hi/lo pairs.
// EPI: 1 = relu -> bf16 hi/lo   2 = +R -> fp32   3 = bf16 hi/lo
//      4 = f16 hi/lo            5 = *log2e -> bf16 hi/lo
#define STG 65536
#define OFF_ALO 16384
#define OFF_BHI 32768
#define OFF_BLO 49152
// swizzled byte offset within a [rows x 64 bf16] tile (128B rows)
#define TSWZ(r, c16) ((uint32_t)((r) * 128 + (((c16) ^ ((r) & 7)) << 4)))

template <int EPI>
__global__ __launch_bounds__(256) void gemm_mma_kernel(
    const __nv_bfloat16* __restrict__ Ahi, const __nv_bfloat16* __restrict__ Alo,
    const __nv_bfloat16* __restrict__ Bhi, const __nv_bfloat16* __restrict__ Blo,
    const float* __restrict__ R, float* __restrict__ Cf,
    __nv_bfloat16* __restrict__ Chi, __nv_bfloat16* __restrict__ Clo,
    int N, int K)
{
    extern __shared__ char smem[];
    uint32_t sb = smem_to_u32(smem);
    int tid = threadIdx.x;
    int wid = tid >> 5, lane = tid & 31;
    int bm = blockIdx.y * 128, bn = blockIdx.x * 128;

    int lr0 = tid >> 3, lc = tid & 7;
    uint32_t soff[4];
    uint32_t ofsA[4], ofsB[4];
    #pragma unroll
    for (int it = 0; it < 4; it++) {
        int r = lr0 + it * 32;
        soff[it] = TSWZ(r, lc);
        ofsA[it] = (uint32_t)((bm + r) * K + lc * 8);
        ofsB[it] = (uint32_t)((bn + r) * K + lc * 8);
    }

    #define ISSUE(s, kt) do {                                                   \
        uint32_t _b = sb + (uint32_t)(s) * STG;                                 \
        uint32_t _ko = (uint32_t)(kt) * 64;                                     \
        _Pragma("unroll")                                                       \
        for (int _it = 0; _it < 4; _it++) {                                     \
            cpasync16(_b + soff[_it],           Ahi + ofsA[_it] + _ko);         \
            cpasync16(_b + OFF_ALO + soff[_it], Alo + ofsA[_it] + _ko);         \
            cpasync16(_b + OFF_BHI + soff[_it], Bhi + ofsB[_it] + _ko);         \
            cpasync16(_b + OFF_BLO + soff[_it], Blo + ofsB[_it] + _ko);         \
        }                                                                       \
        cpasync_commit();                                                       \
    } while (0)

    float acc[2][8][4];
    #pragma unroll
    for (int ma = 0; ma < 2; ma++)
        #pragma unroll
        for (int na = 0; na < 8; na++)
            #pragma unroll
            for (int j = 0; j < 4; j++) acc[ma][na][j] = 0.f;

    int wm = wid & 3, wn = wid >> 2;
    int arow = wm * 32 + (lane & 15);
    int ac16 = lane >> 4;
    int brow = wn * 64 + (lane & 7) + ((lane >> 4) & 1) * 8;
    int bc16 = (lane >> 3) & 1;

    const int NC = K >> 6;
    ISSUE(0, 0);

    #pragma unroll 1
    for (int kt = 0; kt < NC; kt++) {
        if (kt + 1 < NC) { ISSUE((kt + 1) & 1, kt + 1); cpasync_wait1(); }
        else             { cpasync_wait0(); }
        __syncthreads();

        uint32_t ab = sb + (uint32_t)(kt & 1) * STG;
        #pragma unroll
        for (int kk = 0; kk < 4; kk++) {
            uint32_t ah[2][4], al[2][4];
            #pragma unroll
            for (int ma = 0; ma < 2; ma++) {
                int r = arow + ma * 16;
                uint32_t ad = ab + TSWZ(r, ac16 + kk * 2);
                ldsm4(ah[ma], ad);
                ldsm4(al[ma], ad + OFF_ALO);
            }
            #pragma unroll
            for (int np = 0; np < 4; np++) {
                int n = brow + np * 16;
                uint32_t bd = ab + OFF_BHI + TSWZ(n, bc16 + kk * 2);
                uint32_t bh[4], bl[4];
                ldsm4(bh, bd);
                ldsm4(bl, bd + 16384);
                #pragma unroll
                for (int ma = 0; ma < 2; ma++) {
                    mma16816(acc[ma][np*2],   ah[ma], bh);
                    mma16816(acc[ma][np*2+1], ah[ma], bh + 2);
                    mma16816(acc[ma][np*2],   ah[ma], bl);
                    mma16816(acc[ma][np*2+1], ah[ma], bl + 2);
                    mma16816(acc[ma][np*2],   al[ma], bh);
                    mma16816(acc[ma][np*2+1], al[ma], bh + 2);
                }
            }
        }
        __syncthreads();
    }

    // epilogue
    int g = lane >> 2, tg = lane & 3;
    #pragma unroll
    for (int ma = 0; ma < 2; ma++) {
        #pragma unroll
        for (int na = 0; na < 8; na++) {
            int row = bm + wm * 32 + ma * 16 + g;
            int col = bn + wn * 64 + na * 8 + tg * 2;
            float* c = acc[ma][na];
            size_t o0 = (size_t)row * N + col;
            size_t o1 = (size_t)(row + 8) * N + col;
            if (EPI == 1 || EPI == 3 || EPI == 5) {
                float v0 = c[0], v1 = c[1], v2 = c[2], v3 = c[3];
                if (EPI == 1) {
                    v0 = fmaxf(v0, 0.f); v1 = fmaxf(v1, 0.f);
                    v2 = fmaxf(v2, 0.f); v3 = fmaxf(v3, 0.f);
                }
                if (EPI == 5) { v0 *= L2E; v1 *= L2E; v2 *= L2E; v3 *= L2E; }
                __nv_bfloat16 h0[2], l0[2], h1[2], l1[2];
                split_bf16(v0, h0[0], l0[0]); split_bf16(v1, h0[1], l0[1]);
                split_bf16(v2, h1[0], l1[0]); split_bf16(v3, h1[1], l1[1]);
                *(uint32_t*)(Chi + o0) = *(uint32_t*)h0;
                *(uint32_t*)(Clo + o0) = *(uint32_t*)l0;
                *(uint32_t*)(Chi + o1) = *(uint32_t*)h1;
                *(uint32_t*)(Clo + o1) = *(uint32_t*)l1;
            } else if (EPI == 4) {
                __half* Hh = (__half*)Chi;
                __half* Hl = (__half*)Clo;
                __half h0[2], l0[2], h1[2], l1[2];
                split_f16(c[0], h0[0], l0[0]); split_f16(c[1], h0[1], l0[1]);
                split_f16(c[2], h1[0], l1[0]); split_f16(c[3], h1[1], l1[1]);
                *(uint32_t*)(Hh + o0) = *(uint32_t*)h0;
                *(uint32_t*)(Hl + o0) = *(uint32_t*)l0;
                *(uint32_t*)(Hh + o1) = *(uint32_t*)h1;
                *(uint32_t*)(Hl + o1) = *(uint32_t*)l1;
            } else {
                float2 v0 = make_float2(c[0], c[1]);
                float2 v1 = make_float2(c[2], c[3]);
                if (EPI == 2) {
                    float2 r0 = *(const float2*)(R + o0);
                    float2 r1 = *(const float2*)(R + o1);
                    v0.x += r0.x; v0.y += r0.y;
                    v1.x += r1.x; v1.y += r1.y;
                }
                *(float2*)(Cf + o0) = v0;
                *(float2*)(Cf + o1) = v1;
            }
        }
    }
    #undef ISSUE
}

// ---------------- tensor-core flash attention --------------------------------
// grid (S/128, H, B), 256 threads (8 warps x 16 query rows).
// Q pre-scaled by log2e (bf16 hi/lo). K bf16 hi/lo. V fp16 hi/lo.
// Softmax in 2^x domain; exp via ex2.approx.f16x2; P frags are the exp output.
// l accumulated by MMA against an all-ones fp16 B fragment.
#define AQ_HI 0u
#define AQ_LO 16384u
#define AKV0  32768u
#define AKV_STG 32768u
#define A_SMEM (32768u + 2u*32768u)

__global__ __launch_bounds__(256) void attn_mma_kernel(
    const __nv_bfloat16* __restrict__ Qhi, const __nv_bfloat16* __restrict__ Qlo,
    const __nv_bfloat16* __restrict__ Khi, const __nv_bfloat16* __restrict__ Klo,
    const __half* __restrict__ Vhi, const __half* __restrict__ Vlo,
    const float* __restrict__ bias,
    __nv_bfloat16* __restrict__ chi, __nv_bfloat16* __restrict__ clo)
{
    extern __shared__ char smem[];
    uint32_t sb = smem_to_u32(smem);
    int tid = threadIdx.x, wid = tid >> 5, lane = tid & 31;
    int qt = blockIdx.x, h = blockIdx.y, b = blockIdx.z;

    // ---- Q load ----
    {
        int r = tid >> 1;
        int cb = (tid & 1) * 4;
        size_t grow = ((size_t)(b * SS + qt * 128 + r)) * DD + h * HD;
        #pragma unroll
        for (int i = 0; i < 4; i++) {
            int c16 = cb + i;
            uint32_t so = TSWZ(r, c16);
            cpasync16(sb + AQ_HI + so, Qhi + grow + c16 * 8);
            cpasync16(sb + AQ_LO + so, Qlo + grow + c16 * 8);
        }
        cpasync_commit();
    }
    // ---- KV tile issue ----
    int kvr = tid & 63;
    int kvcb = (tid >> 6) * 2;
    #define ISSUE_KV(kt, stg) do {                                              \
        uint32_t _bse = sb + AKV0 + (uint32_t)(stg) * AKV_STG;                  \
        size_t _gr = ((size_t)(b * SS + (kt) * 64 + kvr)) * DD + h * HD;        \
        _Pragma("unroll")                                                       \
        for (int _i = 0; _i < 2; _i++) {                                        \
            int _c = kvcb + _i;                                                 \
            uint32_t _so = TSWZ(kvr, _c);                                       \
            cpasync16(_bse + _so,          Khi + _gr + _c * 8);                 \
            cpasync16(_bse + 8192 + _so,   Klo + _gr + _c * 8);                 \
            cpasync16(_bse + 16384 + _so,  Vhi + _gr + _c * 8);                 \
            cpasync16(_bse + 24576 + _so,  Vlo + _gr + _c * 8);                 \
        }                                                                       \
        cpasync_commit();                                                       \
    } while (0)

    ISSUE_KV(0, 0);

    float oacc[8][4];
    #pragma unroll
    for (int na = 0; na < 8; na++)
        #pragma unroll
        for (int j = 0; j < 4; j++) oacc[na][j] = 0.f;
    float lacc[4] = {0.f, 0.f, 0.f, 0.f};
    float m0 = -1e30f, m1 = -1e30f;
    const uint32_t bones[2] = {0x3C003C00u, 0x3C003C00u};   // f16x2 {1,1}

    int arow = wid * 16 + (lane & 15);
    int ac16 = lane >> 4;
    int bro  = (lane & 7) + ((lane >> 4) & 1) * 8;
    int bc16 = (lane >> 3) & 1;
    int vro  = lane & 15;
    int vch  = lane >> 4;

    size_t brow0 = ((size_t)(b * HH + h) * SS + (qt * 128 + wid * 16 + (lane >> 2))) * SS
                   + 2 * (lane & 3);
    size_t brow1 = brow0 + 8 * (size_t)SS;

    #pragma unroll 1
    for (int kt = 0; kt < 16; kt++) {
        if (kt + 1 < 16) { ISSUE_KV(kt + 1, (kt + 1) & 1); cpasync_wait1(); }
        else             { cpasync_wait0(); }
        __syncthreads();
        uint32_t kvb = sb + AKV0 + (uint32_t)(kt & 1) * AKV_STG;

        // ---- S = Q K^T (Q pre-scaled by log2e; split 3 terms) ----
        float sacc[8][4];
        #pragma unroll
        for (int na = 0; na < 8; na++)
            #pragma unroll
            for (int j = 0; j < 4; j++) sacc[na][j] = 0.f;
        #pragma unroll
        for (int kk = 0; kk < 4; kk++) {
            uint32_t ah[4], al[4];
            uint32_t ad = sb + AQ_HI + TSWZ(arow, ac16 + kk * 2);
            ldsm4(ah, ad);
            ldsm4(al, ad + AQ_LO);
            #pragma unroll
            for (int ng = 0; ng < 4; ng++) {
                uint32_t bd = kvb + TSWZ(bro + ng * 16, bc16 + kk * 2);
                uint32_t kh[4], kl[4];
                ldsm4(kh, bd);
                ldsm4(kl, bd + 8192);
                mma16816(sacc[ng*2],   ah, kh);
                mma16816(sacc[ng*2+1], ah, kh + 2);
                mma16816(sacc[ng*2],   ah, kl);
                mma16816(sacc[ng*2+1], ah, kl + 2);
                mma16816(sacc[ng*2],   al, kh);
                mma16816(sacc[ng*2+1], al, kh + 2);
            }
        }

        // ---- bias (x log2e) + max ----
        const float* bp0 = bias + brow0 + kt * 64;
        const float* bp1 = bias + brow1 + kt * 64;
        float tm0 = -1e30f, tm1 = -1e30f;
        #pragma unroll
        for (int na = 0; na < 8; na++) {
            float2 bv0 = *(const float2*)(bp0 + na * 8);
            float2 bv1 = *(const float2*)(bp1 + na * 8);
            sacc[na][0] = fmaf(bv0.x, L2E, sacc[na][0]);
            sacc[na][1] = fmaf(bv0.y, L2E, sacc[na][1]);
            sacc[na][2] = fmaf(bv1.x, L2E, sacc[na][2]);
            sacc[na][3] = fmaf(bv1.y, L2E, sacc[na][3]);
            tm0 = fmaxf(tm0, fmaxf(sacc[na][0], sacc[na][1]));
            tm1 = fmaxf(tm1, fmaxf(sacc[na][2], sacc[na][3]));
        }
        tm0 = fmaxf(tm0, __shfl_xor_sync(0xffffffffu, tm0, 1));
        tm0 = fmaxf(tm0, __shfl_xor_sync(0xffffffffu, tm0, 2));
        tm1 = fmaxf(tm1, __shfl_xor_sync(0xffffffffu, tm1, 1));
        tm1 = fmaxf(tm1, __shfl_xor_sync(0xffffffffu, tm1, 2));
        float mn0 = fmaxf(m0, tm0), mn1 = fmaxf(m1, tm1);

        // ---- rescale O/l when max changes ----
        if (mn0 != m0 || mn1 != m1) {
            float c0 = ex2f(m0 - mn0), c1 = ex2f(m1 - mn1);
            #pragma unroll
            for (int na = 0; na < 8; na++) {
                oacc[na][0] *= c0; oacc[na][1] *= c0;
                oacc[na][2] *= c1; oacc[na][3] *= c1;
            }
            lacc[0] *= c0; lacc[2] *= c1;
            m0 = mn0; m1 = mn1;
        }

        // ---- p = 2^(t - m) via f16x2; results are P fp16 A-fragments ----
        uint32_t pf[4][4];
        #pragma unroll
        for (int kk = 0; kk < 4; kk++) {
            int n0 = 2 * kk, n1 = 2 * kk + 1;
            pf[kk][0] = ex2h2(packh(sacc[n0][0] - mn0, sacc[n0][1] - mn0));
            pf[kk][1] = ex2h2(packh(sacc[n0][2] - mn1, sacc[n0][3] - mn1));
            pf[kk][2] = ex2h2(packh(sacc[n1][0] - mn0, sacc[n1][1] - mn0));
            pf[kk][3] = ex2h2(packh(sacc[n1][2] - mn1, sacc[n1][3] - mn1));
        }

        // ---- l += row-sums of P (MMA with ones) ----
        #pragma unroll
        for (int kk = 0; kk < 4; kk++)
            mma16816h(lacc, pf[kk], bones);

        // ---- O += P V (V fp16 hi/lo, 2 terms) ----
        #pragma unroll
        for (int kk = 0; kk < 4; kk++) {
            #pragma unroll
            for (int j = 0; j < 4; j++) {
                uint32_t vd = kvb + 16384 + TSWZ(kk * 16 + vro, 2 * j + vch);
                uint32_t vh[4], vl[4];
                ldsm4t(vh, vd);
                ldsm4t(vl, vd + 8192);
                mma16816h(oacc[j*2],   pf[kk], vh);
                mma16816h(oacc[j*2+1], pf[kk], vh + 2);
                mma16816h(oacc[j*2],   pf[kk], vl);
                mma16816h(oacc[j*2+1], pf[kk], vl + 2);
            }
        }
        __syncthreads();
    }

    // ---- epilogue: ctx = O / l, write hi/lo ----
    float il0 = 1.0f / lacc[0], il1 = 1.0f / lacc[2];
    int row0 = b * SS + qt * 128 + wid * 16 + (lane >> 2);
    int colb = h * HD + 2 * (lane & 3);
    #pragma unroll
    for (int na = 0; na < 8; na++) {
        size_t o0 = (size_t)row0 * DD + colb + na * 8;
        size_t o1 = o0 + 8 * (size_t)DD;
        __nv_bfloat16 hh[2], ll[2];
        split_bf16(oacc[na][0] * il0, hh[0], ll[0]);
        split_bf16(oacc[na][1] * il0, hh[1], ll[1]);
        *(uint32_t*)(chi + o0) = *(uint32_t*)hh;
        *(uint32_t*)(clo + o0) = *(uint32_t*)ll;
        split_bf16(oacc[na][2] * il1, hh[0], ll[0]);
        split_bf16(oacc[na][3] * il1, hh[1], ll[1]);
        *(uint32_t*)(chi + o1) = *(uint32_t*)hh;
        *(uint32_t*)(clo + o1) = *(uint32_t*)ll;
    }
    #undef ISSUE_KV
}

// ---------------- launch -----------------------------------------------------
extern "C" void kernel_launch(void* const* d_in, const int* in_sizes, int n_in,
                              void* d_out, int out_size)
{
    const float* Wk   = (const float*)d_in[0];
    const float* Wo   = (const float*)d_in[1];
    const float* Wq   = (const float*)d_in[2];
    const float* Wv   = (const float*)d_in[3];
    const float* ln1  = (const float*)d_in[4];
    const float* W1   = (const float*)d_in[5];
    const float* W2   = (const float*)d_in[6];
    const float* ln2  = (const float*)d_in[7];
    const float* x    = (const float*)d_in[8];
    const float* bias = (const float*)d_in[9];
    float* out = (float*)d_out;

    #define SYM(p, s) void* p; cudaGetSymbolAddress(&p, s)
    SYM(hhi, g_hhi);  SYM(hlo, g_hlo);
    SYM(qhi, g_qhi);  SYM(qlo, g_qlo);
    SYM(khi, g_khi);  SYM(klo, g_klo);
    SYM(vhi, g_vhi);  SYM(vlo, g_vlo);
    SYM(chi, g_chi);  SYM(clo, g_clo);
    SYM(px2, g_x2);
    SYM(h2hi, g_h2hi); SYM(h2lo, g_h2lo);
    SYM(fhi, g_fhi);  SYM(flo, g_flo);
    SYM(wqh, g_wqhi); SYM(wql, g_wqlo);
    SYM(wkh, g_wkhi); SYM(wkl, g_wklo);
    SYM(wvh, g_wvhi); SYM(wvl, g_wvlo);
    SYM(woh, g_wohi); SYM(wol, g_wolo);
    SYM(w1h, g_w1hi); SYM(w1l, g_w1lo);
    SYM(w2h, g_w2hi); SYM(w2l, g_w2lo);
    #undef SYM

    static bool attr_set = false;
    if (!attr_set) {
        cudaFuncSetAttribute(gemm_mma_kernel<1>, cudaFuncAttributeMaxDynamicSharedMemorySize, 2*STG);
        cudaFuncSetAttribute(gemm_mma_kernel<2>, cudaFuncAttributeMaxDynamicSharedMemorySize, 2*STG);
        cudaFuncSetAttribute(gemm_mma_kernel<3>, cudaFuncAttributeMaxDynamicSharedMemorySize, 2*STG);
        cudaFuncSetAttribute(gemm_mma_kernel<4>, cudaFuncAttributeMaxDynamicSharedMemorySize, 2*STG);
        cudaFuncSetAttribute(gemm_mma_kernel<5>, cudaFuncAttributeMaxDynamicSharedMemorySize, 2*STG);
        cudaFuncSetAttribute(attn_mma_kernel, cudaFuncAttributeMaxDynamicSharedMemorySize, A_SMEM);
        attr_set = true;
    }

    typedef const __nv_bfloat16* cbf;
    typedef __nv_bfloat16* bf;

    // fused weight conversions (one launch)
    CvtArgs ca;
    ca.s[0] = Wq; ca.h[0] = (bf)wqh; ca.l[0] = (bf)wql; ca.n4[0] = DD*DD/4;
    ca.s[1] = Wk; ca.h[1] = (bf)wkh; ca.l[1] = (bf)wkl; ca.n4[1] = DD*DD/4;
    ca.s[2] = Wv; ca.h[2] = (bf)wvh; ca.l[2] = (bf)wvl; ca.n4[2] = DD*DD/4;
    ca.s[3] = Wo; ca.h[3] = (bf)woh; ca.l[3] = (bf)wol; ca.n4[3] = DD*DD/4;
    ca.s[4] = W1; ca.h[4] = (bf)w1h; ca.l[4] = (bf)w1l; ca.n4[4] = FF*DD/4;
    ca.s[5] = W2; ca.h[5] = (bf)w2h; ca.l[5] = (bf)w2l; ca.n4[5] = DD*FF/4;
    dim3 gc(FF*DD/4/256, 6);
    cvt6_kernel<<<gc, 256>>>(ca);

    // 1. h = rmsnorm(x, ln1) -> hi/lo
    rmsnorm_kernel<<<NROWS, 256>>>(x, ln1, (bf)hhi, (bf)hlo);

    // 2-4. q/k/v = h @ W^T
    dim3 gD(DD/128, NROWS/128);
    gemm_mma_kernel<5><<<gD, 256, 2*STG>>>((cbf)hhi, (cbf)hlo, (cbf)wqh, (cbf)wql,
                                           nullptr, nullptr, (bf)qhi, (bf)qlo, DD, DD);
    gemm_mma_kernel<3><<<gD, 256, 2*STG>>>((cbf)hhi, (cbf)hlo, (cbf)wkh, (cbf)wkl,
                                           nullptr, nullptr, (bf)khi, (bf)klo, DD, DD);
    gemm_mma_kernel<4><<<gD, 256, 2*STG>>>((cbf)hhi, (cbf)hlo, (cbf)wvh, (cbf)wvl,
                                           nullptr, nullptr, (bf)vhi, (bf)vlo, DD, DD);

    // 5. attention -> ctx hi/lo
    dim3 ga(SS/128, HH, BB);
    attn_mma_kernel<<<ga, 256, A_SMEM>>>((cbf)qhi, (cbf)qlo, (cbf)khi, (cbf)klo,
                                         (const __half*)vhi, (const __half*)vlo,
                                         bias, (bf)chi, (bf)clo);

    // 6. x2 = x + ctx @ Wo^T (fp32)
    gemm_mma_kernel<2><<<gD, 256, 2*STG>>>((cbf)chi, (cbf)clo, (cbf)woh, (cbf)wol,
                                           x, (float*)px2, nullptr, nullptr, DD, DD);

    // 7. h2 = rmsnorm(x2, ln2) -> hi/lo
    rmsnorm_kernel<<<NROWS, 256>>>((const float*)px2, ln2, (bf)h2hi, (bf)h2lo);

    // 8. ff = relu(h2 @ W1^T) -> hi/lo
    dim3 gF(FF/128, NROWS/128);
    gemm_mma_kernel<1><<<gF, 256, 2*STG>>>((cbf)h2hi, (cbf)h2lo, (cbf)w1h, (cbf)w1l,
                                           nullptr, nullptr, (bf)fhi, (bf)flo, FF, DD);

    // 9. out = x2 + ff @ W2^T (fp32)
    gemm_mma_kernel<2><<<gD, 256, 2*STG>>>((cbf)fhi, (cbf)flo, (cbf)w2h, (cbf)w2l,
                                           (const float*)px2, out, nullptr, nullptr, DD, FF);
}